// round 1
// baseline (speedup 1.0000x reference)
#include <cuda_runtime.h>
#include <math.h>

#define N 100000
#define E 400000
#define HID 128
#define NH 8
#define HD 16

// ---------------- device scratch ----------------
__device__ __align__(16) float g_h_a[(size_t)N * HID];
__device__ __align__(16) float g_h_b[(size_t)N * HID];
__device__ __align__(16) float g_alphaS[4][(size_t)N * NH];
__device__ __align__(16) float g_alphaD[4][(size_t)N * NH];
__device__ int   g_deg[4][N];
__device__ int   g_rowptr[4][N + 1];
__device__ int   g_srcs[4][E];
__device__ __align__(16) float g_o[4][(size_t)N * HID];
__device__ float g_score[4];
__device__ float g_attn[4];
__device__ float g_bnsum[2][HID];
__device__ float g_bnsq[2][HID];
__device__ float g_scale[2][HID];
__device__ float g_shift[2][HID];

__device__ __forceinline__ float neg_inf() { return __int_as_float(0xff800000); }

// ---------------- init ----------------
__global__ void init_kernel() {
    int i = blockIdx.x * blockDim.x + threadIdx.x;
    int stride = gridDim.x * blockDim.x;
    int* degf = &g_deg[0][0];
    for (int k = i; k < 4 * N; k += stride) degf[k] = 0;
    if (i < 4) g_score[i] = 0.f;
    if (i < 2 * HID) {
        (&g_bnsum[0][0])[i] = 0.f;
        (&g_bnsq[0][0])[i]  = 0.f;
    }
}

// ---------------- projection GEMM: H = X @ W + b ----------------
// block: 256 threads, tile 64 rows x 128 cols, full K=128.
__global__ void proj_gemm_kernel(const float* __restrict__ A,
                                 const float* __restrict__ W,
                                 const float* __restrict__ bias,
                                 int isA) {
    extern __shared__ float sh[];
    float* As = sh;              // 64*128
    float* Ws = sh + 64 * 128;   // 128*128
    float* Hout = isA ? g_h_a : g_h_b;

    int t = threadIdx.x;
    int row0 = blockIdx.x * 64;

    const float4* W4 = (const float4*)W;
    float4* Ws4 = (float4*)Ws;
#pragma unroll
    for (int i = 0; i < 16; i++) Ws4[i * 256 + t] = W4[i * 256 + t];

    const float4* A4 = (const float4*)A;
    float4* As4 = (float4*)As;
#pragma unroll
    for (int i = 0; i < 8; i++) {
        int idx = i * 256 + t;     // [0,2048)
        int r = idx >> 5, c = idx & 31;
        float4 v = make_float4(0.f, 0.f, 0.f, 0.f);
        if (row0 + r < N) v = A4[(size_t)(row0 + r) * 32 + c];
        As4[idx] = v;
    }
    __syncthreads();

    int tx = t & 31, ty = t >> 5;
    float acc[8][4];
#pragma unroll
    for (int i = 0; i < 8; i++)
#pragma unroll
        for (int c = 0; c < 4; c++) acc[i][c] = 0.f;

    const float* Abase = As + (ty * 8) * 128;
#pragma unroll 8
    for (int k = 0; k < 128; k++) {
        float4 wv = ((const float4*)(Ws + k * 128))[tx];
#pragma unroll
        for (int i = 0; i < 8; i++) {
            float a = Abase[i * 128 + k];
            acc[i][0] = fmaf(a, wv.x, acc[i][0]);
            acc[i][1] = fmaf(a, wv.y, acc[i][1]);
            acc[i][2] = fmaf(a, wv.z, acc[i][2]);
            acc[i][3] = fmaf(a, wv.w, acc[i][3]);
        }
    }
    float4 bv = ((const float4*)bias)[tx];
#pragma unroll
    for (int i = 0; i < 8; i++) {
        int r = row0 + ty * 8 + i;
        if (r < N) {
            float4 o = make_float4(acc[i][0] + bv.x, acc[i][1] + bv.y,
                                   acc[i][2] + bv.z, acc[i][3] + bv.w);
            ((float4*)(Hout + (size_t)r * 128))[tx] = o;
        }
    }
}

// ---------------- alpha: per-node per-head dot(h, att) ----------------
__global__ void alpha_kernel(int isA,
                             const float* __restrict__ attS0, const float* __restrict__ attS1,
                             const float* __restrict__ attD0, const float* __restrict__ attD1,
                             int rS0, int rS1, int rD0, int rD1) {
    const float* h = isA ? g_h_a : g_h_b;
    int t = threadIdx.x;  // 128
    float a0 = attS0[t], a1 = attS1[t], a2 = attD0[t], a3 = attD1[t];
    int hh = t >> 4;
    bool leader = ((t & 15) == 0);
    for (int n = blockIdx.x; n < N; n += gridDim.x) {
        float v = h[(size_t)n * 128 + t];
        float p0 = v * a0, p1 = v * a1, p2 = v * a2, p3 = v * a3;
#pragma unroll
        for (int off = 8; off >= 1; off >>= 1) {
            p0 += __shfl_down_sync(0xffffffff, p0, off, 16);
            p1 += __shfl_down_sync(0xffffffff, p1, off, 16);
            p2 += __shfl_down_sync(0xffffffff, p2, off, 16);
            p3 += __shfl_down_sync(0xffffffff, p3, off, 16);
        }
        if (leader) {
            g_alphaS[rS0][n * NH + hh] = p0;
            g_alphaS[rS1][n * NH + hh] = p1;
            g_alphaD[rD0][n * NH + hh] = p2;
            g_alphaD[rD1][n * NH + hh] = p3;
        }
    }
}

// ---------------- CSR build ----------------
__global__ void count_kernel(const int* __restrict__ ei, int rel) {
    int e = blockIdx.x * blockDim.x + threadIdx.x;
    if (e < E) atomicAdd(&g_deg[rel][ei[E + e]], 1);
}

__global__ void scan_kernel() {
    int rel = blockIdx.x;
    int t = threadIdx.x;  // 1024
    __shared__ int buf[1024];
    int carry = 0;
    for (int base = 0; base < N; base += 1024) {
        int v = (base + t < N) ? g_deg[rel][base + t] : 0;
        int x = v;
        buf[t] = x;
        __syncthreads();
        for (int off = 1; off < 1024; off <<= 1) {
            int y = (t >= off) ? buf[t - off] : 0;
            __syncthreads();
            x += y;
            buf[t] = x;
            __syncthreads();
        }
        if (base + t < N) {
            g_rowptr[rel][base + t] = carry + x - v;
            g_deg[rel][base + t] = 0;   // reset cursor for scatter
        }
        int total = buf[1023];
        __syncthreads();
        carry += total;
    }
    if (t == 0) g_rowptr[rel][N] = carry;
}

__global__ void scatter_kernel(const int* __restrict__ ei, int rel) {
    int e = blockIdx.x * blockDim.x + threadIdx.x;
    if (e < E) {
        int s = ei[e], d = ei[E + e];
        int pos = g_rowptr[rel][d] + atomicAdd(&g_deg[rel][d], 1);
        g_srcs[rel][pos] = s;
    }
}

// ---------------- fused per-dst softmax aggregate ----------------
// one warp per dst node; lane l handles dims [4l,4l+4), head = l/4
__global__ void aggregate_kernel(int rel, int srcIsA) {
    const float* hs = srcIsA ? g_h_a : g_h_b;
    int gwarp = (blockIdx.x * blockDim.x + threadIdx.x) >> 5;
    int lane = threadIdx.x & 31;
    if (gwarp >= N) return;
    int n = gwarp;
    int h = lane >> 2;

    const float* aS = g_alphaS[rel];
    float ad = g_alphaD[rel][n * NH + h];
    int beg = g_rowptr[rel][n], end = g_rowptr[rel][n + 1];
    const int* srcs = g_srcs[rel];

    float m = neg_inf();
    for (int e = beg; e < end; e++) {
        float a = aS[srcs[e] * NH + h] + ad;
        a = a > 0.f ? a : 0.2f * a;
        m = fmaxf(m, a);
    }
    float den = 0.f;
    for (int e = beg; e < end; e++) {
        float a = aS[srcs[e] * NH + h] + ad;
        a = a > 0.f ? a : 0.2f * a;
        den += __expf(a - m);
    }
    float inv = 1.f / (den + 1e-16f);
    float4 acc = make_float4(0.f, 0.f, 0.f, 0.f);
    for (int e = beg; e < end; e++) {
        int s = srcs[e];
        float a = aS[s * NH + h] + ad;
        a = a > 0.f ? a : 0.2f * a;
        float w = __expf(a - m) * inv;
        float4 hv = *reinterpret_cast<const float4*>(hs + (size_t)s * 128 + lane * 4);
        acc.x = fmaf(w, hv.x, acc.x);
        acc.y = fmaf(w, hv.y, acc.y);
        acc.z = fmaf(w, hv.z, acc.z);
        acc.w = fmaf(w, hv.w, acc.w);
    }
    float4 outv = make_float4(fmaxf(acc.x, 0.f), fmaxf(acc.y, 0.f),
                              fmaxf(acc.z, 0.f), fmaxf(acc.w, 0.f));
    *reinterpret_cast<float4*>(&g_o[rel][(size_t)n * 128 + lane * 4]) = outv;
}

// ---------------- semantic score: sum_n tanh(o_n @ Wk + bk) . q ----------------
__global__ void semantic_kernel(const float* __restrict__ Wk,
                                const float* __restrict__ bk,
                                const float* __restrict__ q, int rel) {
    extern __shared__ float sh[];
    float* As = sh;
    float* Ws = sh + 64 * 128;
    const float* A = g_o[rel];

    int t = threadIdx.x;
    int row0 = blockIdx.x * 64;

    const float4* W4 = (const float4*)Wk;
    float4* Ws4 = (float4*)Ws;
#pragma unroll
    for (int i = 0; i < 16; i++) Ws4[i * 256 + t] = W4[i * 256 + t];

    const float4* A4 = (const float4*)A;
    float4* As4 = (float4*)As;
#pragma unroll
    for (int i = 0; i < 8; i++) {
        int idx = i * 256 + t;
        int r = idx >> 5, c = idx & 31;
        float4 v = make_float4(0.f, 0.f, 0.f, 0.f);
        if (row0 + r < N) v = A4[(size_t)(row0 + r) * 32 + c];
        As4[idx] = v;
    }
    __syncthreads();

    int tx = t & 31, ty = t >> 5;
    float acc[8][4];
#pragma unroll
    for (int i = 0; i < 8; i++)
#pragma unroll
        for (int c = 0; c < 4; c++) acc[i][c] = 0.f;

    const float* Abase = As + (ty * 8) * 128;
#pragma unroll 8
    for (int k = 0; k < 128; k++) {
        float4 wv = ((const float4*)(Ws + k * 128))[tx];
#pragma unroll
        for (int i = 0; i < 8; i++) {
            float a = Abase[i * 128 + k];
            acc[i][0] = fmaf(a, wv.x, acc[i][0]);
            acc[i][1] = fmaf(a, wv.y, acc[i][1]);
            acc[i][2] = fmaf(a, wv.z, acc[i][2]);
            acc[i][3] = fmaf(a, wv.w, acc[i][3]);
        }
    }
    float4 bv = ((const float4*)bk)[tx];
    float4 qv = ((const float4*)q)[tx];
    float local = 0.f;
#pragma unroll
    for (int i = 0; i < 8; i++) {
        int r = row0 + ty * 8 + i;
        if (r < N) {
            local += tanhf(acc[i][0] + bv.x) * qv.x;
            local += tanhf(acc[i][1] + bv.y) * qv.y;
            local += tanhf(acc[i][2] + bv.z) * qv.z;
            local += tanhf(acc[i][3] + bv.w) * qv.w;
        }
    }
    __syncthreads();
    float* red = sh;
    red[t] = local;
    __syncthreads();
    for (int s = 128; s > 0; s >>= 1) {
        if (t < s) red[t] += red[t + s];
        __syncthreads();
    }
    if (t == 0) atomicAdd(&g_score[rel], red[0]);
}

// ---------------- semantic softmax ----------------
__global__ void attn_kernel() {
    // type a: rels {1 (ba), 2 (aa)} -> g_attn[0], g_attn[1]
    // type b: rels {0 (ab), 3 (bb)} -> g_attn[2], g_attn[3]
    float sa0 = g_score[1] / (float)N, sa1 = g_score[2] / (float)N;
    float ma = fmaxf(sa0, sa1);
    float ea0 = expf(sa0 - ma), ea1 = expf(sa1 - ma);
    g_attn[0] = ea0 / (ea0 + ea1);
    g_attn[1] = ea1 / (ea0 + ea1);
    float sb0 = g_score[0] / (float)N, sb1 = g_score[3] / (float)N;
    float mb = fmaxf(sb0, sb1);
    float eb0 = expf(sb0 - mb), eb1 = expf(sb1 - mb);
    g_attn[2] = eb0 / (eb0 + eb1);
    g_attn[3] = eb1 / (eb0 + eb1);
}

// ---------------- combine + BN stats ----------------
#define ROWS_PER 256
__global__ void combine_kernel(float* __restrict__ outbuf, int type) {
    int j = threadIdx.x;  // 128
    int r0 = blockIdx.x * ROWS_PER;
    const float* o0;
    const float* o1;
    float a0, a1;
    if (type == 0) { o0 = g_o[1]; o1 = g_o[2]; a0 = g_attn[0]; a1 = g_attn[1]; }
    else           { o0 = g_o[0]; o1 = g_o[3]; a0 = g_attn[2]; a1 = g_attn[3]; }
    float s = 0.f, sq = 0.f;
    int rend = r0 + ROWS_PER;
    if (rend > N) rend = N;
    for (int r = r0; r < rend; r++) {
        float c = a0 * o0[(size_t)r * 128 + j] + a1 * o1[(size_t)r * 128 + j];
        outbuf[(size_t)r * 128 + j] = c;
        s += c;
        sq += c * c;
    }
    atomicAdd(&g_bnsum[type][j], s);
    atomicAdd(&g_bnsq[type][j], sq);
}

__global__ void bnparam_kernel(const float* __restrict__ gamma,
                               const float* __restrict__ beta) {
    int t = threadIdx.x;  // 256
    int type = t >> 7, j = t & 127;
    float mu = g_bnsum[type][j] / (float)N;
    float var = g_bnsq[type][j] / (float)N - mu * mu;
    float rstd = rsqrtf(var + 1e-5f);
    float sc = rstd * gamma[j];
    g_scale[type][j] = sc;
    g_shift[type][j] = beta[j] - mu * sc;
}

__global__ void normalize_kernel(float* __restrict__ out) {
    int stride = gridDim.x * blockDim.x;
    int total = 2 * N * 32;  // float4 elements
    for (int i = blockIdx.x * blockDim.x + threadIdx.x; i < total; i += stride) {
        int j4 = i & 31;
        int type = (i >= N * 32) ? 1 : 0;
        float4 v = ((float4*)out)[i];
        int j = j4 * 4;
        const float* sc = g_scale[type];
        const float* sf = g_shift[type];
        v.x = v.x * sc[j + 0] + sf[j + 0];
        v.y = v.y * sc[j + 1] + sf[j + 1];
        v.z = v.z * sc[j + 2] + sf[j + 2];
        v.w = v.w * sc[j + 3] + sf[j + 3];
        ((float4*)out)[i] = v;
    }
}

// ---------------- host ----------------
extern "C" void kernel_launch(void* const* d_in, const int* in_sizes, int n_in,
                              void* d_out, int out_size) {
    const float* x_a = (const float*)d_in[0];
    const float* x_b = (const float*)d_in[1];
    const int* ei_ab = (const int*)d_in[2];
    const int* ei_ba = (const int*)d_in[3];
    const int* ei_aa = (const int*)d_in[4];
    const int* ei_bb = (const int*)d_in[5];
    const float* W_a = (const float*)d_in[6];
    const float* b_a = (const float*)d_in[7];
    const float* W_b = (const float*)d_in[8];
    const float* b_b = (const float*)d_in[9];
    const float* att_ab_s = (const float*)d_in[10];
    const float* att_ab_d = (const float*)d_in[11];
    const float* att_ba_s = (const float*)d_in[12];
    const float* att_ba_d = (const float*)d_in[13];
    const float* att_aa_s = (const float*)d_in[14];
    const float* att_aa_d = (const float*)d_in[15];
    const float* att_bb_s = (const float*)d_in[16];
    const float* att_bb_d = (const float*)d_in[17];
    const float* Wk = (const float*)d_in[18];
    const float* bk = (const float*)d_in[19];
    const float* q  = (const float*)d_in[20];
    const float* gamma = (const float*)d_in[21];
    const float* beta  = (const float*)d_in[22];
    float* out = (float*)d_out;

    const int smem = 96 * 1024;
    cudaFuncSetAttribute(proj_gemm_kernel, cudaFuncAttributeMaxDynamicSharedMemorySize, smem);
    cudaFuncSetAttribute(semantic_kernel, cudaFuncAttributeMaxDynamicSharedMemorySize, smem);

    init_kernel<<<512, 256>>>();

    int gemmGrid = (N + 63) / 64;
    proj_gemm_kernel<<<gemmGrid, 256, smem>>>(x_a, W_a, b_a, 1);
    proj_gemm_kernel<<<gemmGrid, 256, smem>>>(x_b, W_b, b_b, 0);

    // relations: 0=ab(src a,dst b) 1=ba(src b,dst a) 2=aa 3=bb
    alpha_kernel<<<2048, 128>>>(1, att_ab_s, att_aa_s, att_ba_d, att_aa_d, 0, 2, 1, 2);
    alpha_kernel<<<2048, 128>>>(0, att_ba_s, att_bb_s, att_ab_d, att_bb_d, 1, 3, 0, 3);

    int eGrid = (E + 255) / 256;
    count_kernel<<<eGrid, 256>>>(ei_ab, 0);
    count_kernel<<<eGrid, 256>>>(ei_ba, 1);
    count_kernel<<<eGrid, 256>>>(ei_aa, 2);
    count_kernel<<<eGrid, 256>>>(ei_bb, 3);

    scan_kernel<<<4, 1024>>>();

    scatter_kernel<<<eGrid, 256>>>(ei_ab, 0);
    scatter_kernel<<<eGrid, 256>>>(ei_ba, 1);
    scatter_kernel<<<eGrid, 256>>>(ei_aa, 2);
    scatter_kernel<<<eGrid, 256>>>(ei_bb, 3);

    int aggGrid = (N * 32 + 255) / 256;
    aggregate_kernel<<<aggGrid, 256>>>(0, 1);
    aggregate_kernel<<<aggGrid, 256>>>(1, 0);
    aggregate_kernel<<<aggGrid, 256>>>(2, 1);
    aggregate_kernel<<<aggGrid, 256>>>(3, 0);

    semantic_kernel<<<gemmGrid, 256, smem>>>(Wk, bk, q, 0);
    semantic_kernel<<<gemmGrid, 256, smem>>>(Wk, bk, q, 1);
    semantic_kernel<<<gemmGrid, 256, smem>>>(Wk, bk, q, 2);
    semantic_kernel<<<gemmGrid, 256, smem>>>(Wk, bk, q, 3);

    attn_kernel<<<1, 1>>>();

    int cGrid = (N + ROWS_PER - 1) / ROWS_PER;
    combine_kernel<<<cGrid, 128>>>(out, 0);                       // type a -> first half
    combine_kernel<<<cGrid, 128>>>(out + (size_t)N * HID, 1);     // type b -> second half

    bnparam_kernel<<<1, 256>>>(gamma, beta);

    normalize_kernel<<<4096, 256>>>(out);
}

// round 4
// speedup vs baseline: 1.1637x; 1.1637x over previous
#include <cuda_runtime.h>
#include <cuda_bf16.h>
#include <math.h>
#include <stdint.h>

#define N 100000
#define E 400000
#define HID 128
#define NH 8

// ---------------- device scratch ----------------
__device__ __align__(16) float g_h_a[(size_t)N * HID];
__device__ __align__(16) float g_h_b[(size_t)N * HID];
__device__ __align__(16) float g_alphaS[4][(size_t)N * NH];  // layout [n*8 + h]
__device__ __align__(16) float g_alphaD[4][(size_t)N * NH];  // layout [n*8 + h]
__device__ int   g_deg[4][N];
__device__ int   g_rowptr[4][N + 1];
__device__ int   g_bsum[4][128];
__device__ int   g_boff[4][128];
__device__ int   g_srcs[4][E];
__device__ __align__(16) float g_o[4][(size_t)N * HID];
__device__ float g_score[4];
__device__ float g_attn[4];
__device__ float g_bnsum[2][HID];
__device__ float g_bnsq[2][HID];
__device__ float g_scale[2][HID];
__device__ float g_shift[2][HID];
// transposed bf16 hi/lo weights: [which][hi/lo][n*64 + kw] as packed bf16x2
__device__ uint32_t g_Wt[3][2][64 * 128];

// ---------------- helpers ----------------
__device__ __forceinline__ uint32_t bfpair(float x, float y) {
    __nv_bfloat162 p = __floats2bfloat162_rn(x, y);
    return *reinterpret_cast<uint32_t*>(&p);
}

__device__ __forceinline__ void split2(float x, float y, uint32_t& hi, uint32_t& lo) {
    __nv_bfloat16 hx = __float2bfloat16(x), hy = __float2bfloat16(y);
    __nv_bfloat162 hp(hx, hy);
    hi = *reinterpret_cast<uint32_t*>(&hp);
    float lx = x - __bfloat162float(hx);
    float ly = y - __bfloat162float(hy);
    lo = bfpair(lx, ly);
}

__device__ __forceinline__ void mma_bf16(float* d, const uint32_t* a, uint32_t b0, uint32_t b1) {
    asm volatile(
        "mma.sync.aligned.m16n8k16.row.col.f32.bf16.bf16.f32 "
        "{%0,%1,%2,%3}, {%4,%5,%6,%7}, {%8,%9}, {%0,%1,%2,%3};"
        : "+f"(d[0]), "+f"(d[1]), "+f"(d[2]), "+f"(d[3])
        : "r"(a[0]), "r"(a[1]), "r"(a[2]), "r"(a[3]), "r"(b0), "r"(b1));
}

// smem word (u32) layout: AH[128][68], AL, WH, WL ; pitch 68 u32 = 136 bf16
#define SW_AH 0
#define SW_AL 8704
#define SW_WH 17408
#define SW_WL 26112
#define SW_EXTRA 34816          // 512 floats for atts / reductions
#define MM_SMEM_BYTES ((34816 + 512) * 4)

// ---------------- weight prep: transpose + hi/lo split ----------------
__global__ void prep_w_kernel(const float* __restrict__ W_a,
                              const float* __restrict__ W_b,
                              const float* __restrict__ Wk) {
    int which = blockIdx.x;
    const float* W = which == 0 ? W_a : (which == 1 ? W_b : Wk);
    for (int idx = threadIdx.x; idx < 8192; idx += blockDim.x) {
        int n = idx >> 6, kw = idx & 63;
        float v0 = W[(2 * kw) * 128 + n];
        float v1 = W[(2 * kw + 1) * 128 + n];
        uint32_t hi, lo;
        split2(v0, v1, hi, lo);
        g_Wt[which][0][idx] = hi;
        g_Wt[which][1][idx] = lo;
    }
}

// ---------------- core 128x128x128 tile: acc += A @ W (3-pass bf16 split) ----------------
// acc[64]: indexed acc[(rt*8+nt)*4 + r]; warp tile 32 rows x 64 cols
__device__ __forceinline__ void gemm_tile(const float* __restrict__ A, int arows,
                                          int which, uint32_t* smemu, float* acc) {
    int t = threadIdx.x;
    int row0 = blockIdx.x * 128;

    // stage A (hi/lo split)
    const float4* A4 = (const float4*)A;
    for (int idx = t; idx < 4096; idx += 256) {
        int r = idx >> 5, c4 = idx & 31;
        int gr = row0 + r;
        float4 v = make_float4(0.f, 0.f, 0.f, 0.f);
        if (gr < arows) v = A4[(size_t)gr * 32 + c4];
        uint32_t h0, l0, h1, l1;
        split2(v.x, v.y, h0, l0);
        split2(v.z, v.w, h1, l1);
        int base = r * 68 + c4 * 2;
        smemu[SW_AH + base] = h0;
        smemu[SW_AH + base + 1] = h1;
        smemu[SW_AL + base] = l0;
        smemu[SW_AL + base + 1] = l1;
    }
    // stage W (already transposed+split in global)
    const uint32_t* Wh = g_Wt[which][0];
    const uint32_t* Wl = g_Wt[which][1];
    for (int idx = t; idx < 8192; idx += 256) {
        int n = idx >> 6, kw = idx & 63;
        smemu[SW_WH + n * 68 + kw] = Wh[idx];
        smemu[SW_WL + n * 68 + kw] = Wl[idx];
    }
    __syncthreads();

    int wid = t >> 5, lane = t & 31;
    int wr = (wid >> 1) * 32, wc = (wid & 1) * 64;

#pragma unroll
    for (int i = 0; i < 64; i++) acc[i] = 0.f;

    const int AO[3] = {SW_AH, SW_AH, SW_AL};
    const int WO[3] = {SW_WH, SW_WL, SW_WH};
#pragma unroll
    for (int p = 0; p < 3; p++) {
        const uint32_t* Ab = smemu + AO[p] + (wr + (lane >> 2)) * 68 + (lane & 3);
        const uint32_t* Bb = smemu + WO[p] + (wc + (lane >> 2)) * 68 + (lane & 3);
#pragma unroll
        for (int kc = 0; kc < 8; kc++) {
            uint32_t a[2][4];
#pragma unroll
            for (int rt = 0; rt < 2; rt++) {
                const uint32_t* Ap = Ab + rt * 16 * 68 + kc * 8;
                a[rt][0] = Ap[0];
                a[rt][1] = Ap[8 * 68];
                a[rt][2] = Ap[4];
                a[rt][3] = Ap[8 * 68 + 4];
            }
#pragma unroll
            for (int nt = 0; nt < 8; nt++) {
                const uint32_t* Bp = Bb + nt * 8 * 68 + kc * 8;
                uint32_t b0 = Bp[0], b1 = Bp[4];
                mma_bf16(acc + (0 * 8 + nt) * 4, a[0], b0, b1);
                mma_bf16(acc + (1 * 8 + nt) * 4, a[1], b0, b1);
            }
        }
    }
}

// ---------------- projection: H = X@W + b, fused per-head attention dots ----------------
__global__ void __launch_bounds__(256, 1) proj_mma_kernel(
    const float* __restrict__ X, int which, const float* __restrict__ bias, int typeA,
    const float* __restrict__ attS0, const float* __restrict__ attS1,
    const float* __restrict__ attD0, const float* __restrict__ attD1,
    int rS0, int rS1, int rD0, int rD1) {
    extern __shared__ uint32_t smemu[];
    float* smemf = (float*)smemu;
    float* satt = smemf + SW_EXTRA;

    // load attention vectors to smem (before gemm; region untouched by it)
    int t = threadIdx.x;
    for (int i = t; i < 512; i += 256) {
        int arr = i >> 7, col = i & 127;
        const float* p = arr == 0 ? attS0 : arr == 1 ? attS1 : arr == 2 ? attD0 : attD1;
        satt[i] = __ldg(&p[col]);
    }

    float acc[64];
    gemm_tile(X, N, which, smemu, acc);

    float* Hout = typeA ? g_h_a : g_h_b;
    int wid = t >> 5, lane = t & 31;
    int wr = (wid >> 1) * 32, wc = (wid & 1) * 64;
    int row0 = blockIdx.x * 128;

    __syncthreads();  // done reading A smem; reuse as vbuf

    // phase 1: add bias, store H to global, stage v into smem (pitch 134)
#pragma unroll
    for (int rt = 0; rt < 2; rt++) {
#pragma unroll
        for (int hr = 0; hr < 2; hr++) {
            int lrow = wr + rt * 16 + hr * 8 + (lane >> 2);
            int grow = row0 + lrow;
#pragma unroll
            for (int nt = 0; nt < 8; nt++) {
                int col = wc + nt * 8 + (lane & 3) * 2;
                float2 bb = __ldg((const float2*)(bias + col));
                float v0 = acc[(rt * 8 + nt) * 4 + hr * 2] + bb.x;
                float v1 = acc[(rt * 8 + nt) * 4 + hr * 2 + 1] + bb.y;
                if (grow < N)
                    *(float2*)(Hout + (size_t)grow * 128 + col) = make_float2(v0, v1);
                *(float2*)(smemf + lrow * 134 + col) = make_float2(v0, v1);
            }
        }
    }
    __syncthreads();

    // phase 2: per-row per-head attention dots
    if (t < 128) {
        int node = row0 + t;
        if (node < N) {
            const float* vrow = smemf + t * 134;
            float* aS0 = &g_alphaS[rS0][0];
            float* aS1 = &g_alphaS[rS1][0];
            float* aD0 = &g_alphaD[rD0][0];
            float* aD1 = &g_alphaD[rD1][0];
#pragma unroll
            for (int h = 0; h < 8; h++) {
                float p0 = 0.f, p1 = 0.f, p2 = 0.f, p3 = 0.f;
#pragma unroll
                for (int i = 0; i < 16; i++) {
                    int col = h * 16 + i;
                    float v = vrow[col];
                    p0 = fmaf(v, satt[0 * 128 + col], p0);
                    p1 = fmaf(v, satt[1 * 128 + col], p1);
                    p2 = fmaf(v, satt[2 * 128 + col], p2);
                    p3 = fmaf(v, satt[3 * 128 + col], p3);
                }
                aS0[node * 8 + h] = p0;
                aS1[node * 8 + h] = p1;
                aD0[node * 8 + h] = p2;
                aD1[node * 8 + h] = p3;
            }
        }
    }
}

// ---------------- semantic score: sum_n tanh(o_n @ Wk + bk) . q ----------------
__global__ void __launch_bounds__(256, 1) sem_mma_kernel(
    const float* __restrict__ bk, const float* __restrict__ q) {
    extern __shared__ uint32_t smemu[];
    float* red = (float*)smemu + SW_EXTRA;
    int rel = blockIdx.y;

    float acc[64];
    gemm_tile(&g_o[rel][0], N, 2, smemu, acc);

    int t = threadIdx.x;
    int wid = t >> 5, lane = t & 31;
    int wr = (wid >> 1) * 32, wc = (wid & 1) * 64;
    int row0 = blockIdx.x * 128;

    float local = 0.f;
#pragma unroll
    for (int rt = 0; rt < 2; rt++) {
#pragma unroll
        for (int hr = 0; hr < 2; hr++) {
            int grow = row0 + wr + rt * 16 + hr * 8 + (lane >> 2);
            if (grow < N) {
#pragma unroll
                for (int nt = 0; nt < 8; nt++) {
                    int col = wc + nt * 8 + (lane & 3) * 2;
                    float2 bb = __ldg((const float2*)(bk + col));
                    float2 qq = __ldg((const float2*)(q + col));
                    float v0 = acc[(rt * 8 + nt) * 4 + hr * 2] + bb.x;
                    float v1 = acc[(rt * 8 + nt) * 4 + hr * 2 + 1] + bb.y;
                    local += tanhf(v0) * qq.x + tanhf(v1) * qq.y;
                }
            }
        }
    }
#pragma unroll
    for (int off = 16; off >= 1; off >>= 1)
        local += __shfl_down_sync(0xffffffff, local, off);
    __syncthreads();
    if (lane == 0) red[wid] = local;
    __syncthreads();
    if (t == 0) {
        float s = 0.f;
#pragma unroll
        for (int w = 0; w < 8; w++) s += red[w];
        atomicAdd(&g_score[rel], s);
    }
}

// ---------------- init ----------------
__global__ void init_kernel() {
    int i = blockIdx.x * blockDim.x + threadIdx.x;
    int stride = gridDim.x * blockDim.x;
    int* degf = &g_deg[0][0];
    for (int k = i; k < 4 * N; k += stride) degf[k] = 0;
    if (i < 4) g_score[i] = 0.f;
    if (i < 2 * HID) {
        (&g_bnsum[0][0])[i] = 0.f;
        (&g_bnsq[0][0])[i] = 0.f;
    }
}

// ---------------- CSR build ----------------
__global__ void count_kernel(const int* __restrict__ e0, const int* __restrict__ e1,
                             const int* __restrict__ e2, const int* __restrict__ e3) {
    int rel = blockIdx.y;
    const int* ei = rel == 0 ? e0 : rel == 1 ? e1 : rel == 2 ? e2 : e3;
    int e = blockIdx.x * blockDim.x + threadIdx.x;
    if (e < E) atomicAdd(&g_deg[rel][ei[E + e]], 1);
}

__global__ void scan1_kernel() {
    int rel = blockIdx.y;
    int i = blockIdx.x * 1024 + threadIdx.x;
    int lane = threadIdx.x & 31, wid = threadIdx.x >> 5;
    int v = (i < N) ? g_deg[rel][i] : 0;
    int x = v;
#pragma unroll
    for (int o = 1; o < 32; o <<= 1) {
        int y = __shfl_up_sync(0xffffffff, x, o);
        if (lane >= o) x += y;
    }
    __shared__ int ws[32];
    if (lane == 31) ws[wid] = x;
    __syncthreads();
    if (wid == 0) {
        int s = ws[lane];
#pragma unroll
        for (int o = 1; o < 32; o <<= 1) {
            int y = __shfl_up_sync(0xffffffff, s, o);
            if (lane >= o) s += y;
        }
        ws[lane] = s;
    }
    __syncthreads();
    int incl = x + (wid ? ws[wid - 1] : 0);
    if (i < N) g_rowptr[rel][i] = incl - v;
    if (threadIdx.x == 1023) g_bsum[rel][blockIdx.x] = incl;
}

__global__ void scan2_kernel() {
    int rel = blockIdx.x;
    int t = threadIdx.x;  // 128
    int lane = t & 31, wid = t >> 5;
    int v = (t < 98) ? g_bsum[rel][t] : 0;
    int x = v;
#pragma unroll
    for (int o = 1; o < 32; o <<= 1) {
        int y = __shfl_up_sync(0xffffffff, x, o);
        if (lane >= o) x += y;
    }
    __shared__ int ws[4];
    if (lane == 31) ws[wid] = x;
    __syncthreads();
    int prefix = 0;
    for (int k = 0; k < wid; k++) prefix += ws[k];
    int incl = x + prefix;
    if (t < 98) g_boff[rel][t] = incl - v;
    if (t == 0) g_rowptr[rel][N] = E;
}

__global__ void scan3_kernel() {
    int rel = blockIdx.y;
    int i = blockIdx.x * 1024 + threadIdx.x;
    if (i < N) {
        g_rowptr[rel][i] += g_boff[rel][blockIdx.x];
        g_deg[rel][i] = 0;  // reset cursor for scatter
    }
}

__global__ void scatter_kernel(const int* __restrict__ e0, const int* __restrict__ e1,
                               const int* __restrict__ e2, const int* __restrict__ e3) {
    int rel = blockIdx.y;
    const int* ei = rel == 0 ? e0 : rel == 1 ? e1 : rel == 2 ? e2 : e3;
    int e = blockIdx.x * blockDim.x + threadIdx.x;
    if (e < E) {
        int s = ei[e], d = ei[E + e];
        int pos = g_rowptr[rel][d] + atomicAdd(&g_deg[rel][d], 1);
        g_srcs[rel][pos] = s;
    }
}

// ---------------- single-pass fused softmax aggregate ----------------
// one warp per dst node; lane l handles dims [4l,4l+4), head = l/4
__global__ void aggregate_kernel() {
    int rel = blockIdx.y;
    const float* hs = (rel == 0 || rel == 2) ? g_h_a : g_h_b;
    int n = (blockIdx.x * blockDim.x + threadIdx.x) >> 5;
    if (n >= N) return;
    int lane = threadIdx.x & 31;
    int h = lane >> 2;

    const float* aS = g_alphaS[rel];
    float ad = g_alphaD[rel][n * 8 + h];
    int beg = g_rowptr[rel][n], end = g_rowptr[rel][n + 1];
    const int* srcs = g_srcs[rel];

    float den = 0.f;
    float4 acc = make_float4(0.f, 0.f, 0.f, 0.f);
    for (int e = beg; e < end; e++) {
        int s = srcs[e];
        float a = aS[s * 8 + h] + ad;
        a = a > 0.f ? a : 0.2f * a;
        float w = __expf(a);
        den += w;
        float4 hv = *reinterpret_cast<const float4*>(hs + (size_t)s * 128 + lane * 4);
        acc.x = fmaf(w, hv.x, acc.x);
        acc.y = fmaf(w, hv.y, acc.y);
        acc.z = fmaf(w, hv.z, acc.z);
        acc.w = fmaf(w, hv.w, acc.w);
    }
    float inv = 1.f / (den + 1e-16f);
    float4 outv = make_float4(fmaxf(acc.x * inv, 0.f), fmaxf(acc.y * inv, 0.f),
                              fmaxf(acc.z * inv, 0.f), fmaxf(acc.w * inv, 0.f));
    *reinterpret_cast<float4*>(&g_o[rel][(size_t)n * 128 + lane * 4]) = outv;
}

// ---------------- semantic softmax ----------------
__global__ void attn_kernel() {
    float sa0 = g_score[1] / (float)N, sa1 = g_score[2] / (float)N;
    float ma = fmaxf(sa0, sa1);
    float ea0 = expf(sa0 - ma), ea1 = expf(sa1 - ma);
    g_attn[0] = ea0 / (ea0 + ea1);
    g_attn[1] = ea1 / (ea0 + ea1);
    float sb0 = g_score[0] / (float)N, sb1 = g_score[3] / (float)N;
    float mb = fmaxf(sb0, sb1);
    float eb0 = expf(sb0 - mb), eb1 = expf(sb1 - mb);
    g_attn[2] = eb0 / (eb0 + eb1);
    g_attn[3] = eb1 / (eb0 + eb1);
}

// ---------------- combine + BN stats ----------------
#define ROWS_PER 256
__global__ void combine_kernel(float* __restrict__ outbuf, int type) {
    int j = threadIdx.x;  // 128
    int r0 = blockIdx.x * ROWS_PER;
    const float* o0;
    const float* o1;
    float a0, a1;
    if (type == 0) { o0 = g_o[1]; o1 = g_o[2]; a0 = g_attn[0]; a1 = g_attn[1]; }
    else           { o0 = g_o[0]; o1 = g_o[3]; a0 = g_attn[2]; a1 = g_attn[3]; }
    float s = 0.f, sq = 0.f;
    int rend = r0 + ROWS_PER;
    if (rend > N) rend = N;
    for (int r = r0; r < rend; r++) {
        float c = a0 * o0[(size_t)r * 128 + j] + a1 * o1[(size_t)r * 128 + j];
        outbuf[(size_t)r * 128 + j] = c;
        s += c;
        sq += c * c;
    }
    atomicAdd(&g_bnsum[type][j], s);
    atomicAdd(&g_bnsq[type][j], sq);
}

__global__ void bnparam_kernel(const float* __restrict__ gamma,
                               const float* __restrict__ beta) {
    int t = threadIdx.x;  // 256
    int type = t >> 7, j = t & 127;
    float mu = g_bnsum[type][j] / (float)N;
    float var = g_bnsq[type][j] / (float)N - mu * mu;
    float rstd = rsqrtf(var + 1e-5f);
    float sc = rstd * gamma[j];
    g_scale[type][j] = sc;
    g_shift[type][j] = beta[j] - mu * sc;
}

__global__ void normalize_kernel(float* __restrict__ out) {
    int stride = gridDim.x * blockDim.x;
    int total = 2 * N * 32;  // float4 elements
    for (int i = blockIdx.x * blockDim.x + threadIdx.x; i < total; i += stride) {
        int j4 = i & 31;
        int type = (i >= N * 32) ? 1 : 0;
        float4 v = ((float4*)out)[i];
        int j = j4 * 4;
        const float* sc = g_scale[type];
        const float* sf = g_shift[type];
        v.x = v.x * sc[j + 0] + sf[j + 0];
        v.y = v.y * sc[j + 1] + sf[j + 1];
        v.z = v.z * sc[j + 2] + sf[j + 2];
        v.w = v.w * sc[j + 3] + sf[j + 3];
        ((float4*)out)[i] = v;
    }
}

// ---------------- host ----------------
extern "C" void kernel_launch(void* const* d_in, const int* in_sizes, int n_in,
                              void* d_out, int out_size) {
    const float* x_a = (const float*)d_in[0];
    const float* x_b = (const float*)d_in[1];
    const int* ei_ab = (const int*)d_in[2];
    const int* ei_ba = (const int*)d_in[3];
    const int* ei_aa = (const int*)d_in[4];
    const int* ei_bb = (const int*)d_in[5];
    const float* W_a = (const float*)d_in[6];
    const float* b_a = (const float*)d_in[7];
    const float* W_b = (const float*)d_in[8];
    const float* b_b = (const float*)d_in[9];
    const float* att_ab_s = (const float*)d_in[10];
    const float* att_ab_d = (const float*)d_in[11];
    const float* att_ba_s = (const float*)d_in[12];
    const float* att_ba_d = (const float*)d_in[13];
    const float* att_aa_s = (const float*)d_in[14];
    const float* att_aa_d = (const float*)d_in[15];
    const float* att_bb_s = (const float*)d_in[16];
    const float* att_bb_d = (const float*)d_in[17];
    const float* Wk = (const float*)d_in[18];
    const float* bk = (const float*)d_in[19];
    const float* q  = (const float*)d_in[20];
    const float* gamma = (const float*)d_in[21];
    const float* beta  = (const float*)d_in[22];
    float* out = (float*)d_out;

    cudaFuncSetAttribute(proj_mma_kernel, cudaFuncAttributeMaxDynamicSharedMemorySize, MM_SMEM_BYTES);
    cudaFuncSetAttribute(sem_mma_kernel, cudaFuncAttributeMaxDynamicSharedMemorySize, MM_SMEM_BYTES);

    init_kernel<<<512, 256>>>();
    prep_w_kernel<<<3, 256>>>(W_a, W_b, Wk);

    // relations: 0=ab(src a,dst b) 1=ba(src b,dst a) 2=aa 3=bb
    int mmGrid = (N + 127) / 128;  // 782
    // type a: S-dots for rels 0,2 ; D-dots for rels 1,2
    proj_mma_kernel<<<mmGrid, 256, MM_SMEM_BYTES>>>(
        x_a, 0, b_a, 1, att_ab_s, att_aa_s, att_ba_d, att_aa_d, 0, 2, 1, 2);
    // type b: S-dots for rels 1,3 ; D-dots for rels 0,3
    proj_mma_kernel<<<mmGrid, 256, MM_SMEM_BYTES>>>(
        x_b, 1, b_b, 0, att_ba_s, att_bb_s, att_ab_d, att_bb_d, 1, 3, 0, 3);

    dim3 eGrid((E + 255) / 256, 4);
    count_kernel<<<eGrid, 256>>>(ei_ab, ei_ba, ei_aa, ei_bb);

    dim3 sGrid((N + 1023) / 1024, 4);
    scan1_kernel<<<sGrid, 1024>>>();
    scan2_kernel<<<4, 128>>>();
    scan3_kernel<<<sGrid, 1024>>>();

    scatter_kernel<<<eGrid, 256>>>(ei_ab, ei_ba, ei_aa, ei_bb);

    dim3 aggGrid((N * 32 + 255) / 256, 4);
    aggregate_kernel<<<aggGrid, 256>>>();

    dim3 semGrid(mmGrid, 4);
    sem_mma_kernel<<<semGrid, 256, MM_SMEM_BYTES>>>(bk, q);

    attn_kernel<<<1, 1>>>();

    int cGrid = (N + ROWS_PER - 1) / ROWS_PER;
    combine_kernel<<<cGrid, 128>>>(out, 0);
    combine_kernel<<<cGrid, 128>>>(out + (size_t)N * HID, 1);

    bnparam_kernel<<<1, 256>>>(gamma, beta);

    normalize_kernel<<<4096, 256>>>(out);
}

// round 5
// speedup vs baseline: 1.5669x; 1.3464x over previous
#include <cuda_runtime.h>
#include <cuda_bf16.h>
#include <math.h>
#include <stdint.h>

#define N 100000
#define E 400000
#define HID 128
#define NH 8

// ---------------- device scratch ----------------
__device__ __align__(16) float g_h_a[(size_t)N * HID];
__device__ __align__(16) float g_h_b[(size_t)N * HID];
__device__ __align__(16) float g_alphaS[4][(size_t)N * NH];  // layout [n*8 + h]
__device__ __align__(16) float g_alphaD[4][(size_t)N * NH];  // layout [n*8 + h]
__device__ int   g_deg[4][N];
__device__ int   g_rowptr[4][N + 1];
__device__ int   g_bsum[4][128];
__device__ int   g_boff[4][128];
__device__ int   g_srcs[4][E];
__device__ __align__(16) float g_o[4][(size_t)N * HID];
__device__ float g_score[4];
__device__ float g_attn[4];
__device__ float g_bnsum[2][HID];
__device__ float g_bnsq[2][HID];
__device__ float g_scale[2][HID];
__device__ float g_shift[2][HID];
// transposed bf16 hi/lo weights: [which][hi/lo][n*64 + kw] packed bf16x2 (k-major pairs)
__device__ uint32_t g_Wt[3][2][64 * 128];
// pre-split inputs: [type][hi/lo][n*64 + kw] packed bf16x2
__device__ __align__(16) uint32_t g_Xbf[2][2][(size_t)N * 64];
// bf16 copy of o for semantic GEMM: [rel][n*64 + kw]
__device__ __align__(16) uint32_t g_obf[4][(size_t)N * 64];

// ---------------- helpers ----------------
__device__ __forceinline__ uint32_t bfpair(float x, float y) {
    __nv_bfloat162 p = __floats2bfloat162_rn(x, y);
    return *reinterpret_cast<uint32_t*>(&p);
}

__device__ __forceinline__ void split2(float x, float y, uint32_t& hi, uint32_t& lo) {
    __nv_bfloat16 hx = __float2bfloat16(x), hy = __float2bfloat16(y);
    __nv_bfloat162 hp(hx, hy);
    hi = *reinterpret_cast<uint32_t*>(&hp);
    float lx = x - __bfloat162float(hx);
    float ly = y - __bfloat162float(hy);
    lo = bfpair(lx, ly);
}

__device__ __forceinline__ void mma_bf16(float* d, const uint32_t* a, uint32_t b0, uint32_t b1) {
    asm volatile(
        "mma.sync.aligned.m16n8k16.row.col.f32.bf16.bf16.f32 "
        "{%0,%1,%2,%3}, {%4,%5,%6,%7}, {%8,%9}, {%0,%1,%2,%3};"
        : "+f"(d[0]), "+f"(d[1]), "+f"(d[2]), "+f"(d[3])
        : "r"(a[0]), "r"(a[1]), "r"(a[2]), "r"(a[3]), "r"(b0), "r"(b1));
}

__device__ __forceinline__ uint32_t smem_u32(const void* p) {
    uint32_t a;
    asm("{ .reg .u64 t; cvta.to.shared.u64 t, %1; cvt.u32.u64 %0, t; }" : "=r"(a) : "l"(p));
    return a;
}

// stage a 128-row x 64-u32 tile (pitch 68 u32) from global via cp.async, 16B chunks
__device__ __forceinline__ void stage_tile(uint32_t sbase_bytes, const uint32_t* __restrict__ src,
                                           int row0, int arows) {
    int t = threadIdx.x;
#pragma unroll
    for (int i = 0; i < 8; i++) {
        int idx = i * 256 + t;            // [0, 2048)
        int r = idx >> 4, c = idx & 15;
        int gr = row0 + r;
        bool ok = (gr < arows);
        const uint32_t* s = src + (size_t)(ok ? gr : 0) * 64 + c * 4;
        uint32_t dst = sbase_bytes + (r * 68 + c * 4) * 4;
        int sz = ok ? 16 : 0;
        asm volatile("cp.async.cg.shared.global [%0], [%1], 16, %2;" :: "r"(dst), "l"(s), "r"(sz));
    }
}

#define CP_COMMIT_WAIT() do { \
    asm volatile("cp.async.commit_group;" ::: "memory"); \
    asm volatile("cp.async.wait_group 0;" ::: "memory"); \
} while (0)

// ---------------- GEMM compute: acc += sum_p A[p] @ W[p] on staged tiles ----------------
// 8 warps, warp tile 32 rows x 64 cols; acc[(rt*8+nt)*4 + r]
template <int NPASS>
__device__ __forceinline__ void gemm_compute(const uint32_t* __restrict__ smemu,
                                             const int* AO, const int* WO, float* acc) {
    int t = threadIdx.x;
    int wid = t >> 5, lane = t & 31;
    int wr = (wid >> 1) * 32, wc = (wid & 1) * 64;

#pragma unroll
    for (int i = 0; i < 64; i++) acc[i] = 0.f;

#pragma unroll
    for (int p = 0; p < NPASS; p++) {
        const uint32_t* Ab = smemu + AO[p] + (wr + (lane >> 2)) * 68 + (lane & 3);
        const uint32_t* Bb = smemu + WO[p] + (wc + (lane >> 2)) * 68 + (lane & 3);
#pragma unroll 2
        for (int kc = 0; kc < 8; kc++) {
            uint32_t a[2][4];
#pragma unroll
            for (int rt = 0; rt < 2; rt++) {
                const uint32_t* Ap = Ab + rt * 16 * 68 + kc * 8;
                a[rt][0] = Ap[0];
                a[rt][1] = Ap[8 * 68];
                a[rt][2] = Ap[4];
                a[rt][3] = Ap[8 * 68 + 4];
            }
#pragma unroll
            for (int nt = 0; nt < 8; nt++) {
                const uint32_t* Bp = Bb + nt * 8 * 68 + kc * 8;
                uint32_t b0 = Bp[0], b1 = Bp[4];
                mma_bf16(acc + (0 * 8 + nt) * 4, a[0], b0, b1);
                mma_bf16(acc + (1 * 8 + nt) * 4, a[1], b0, b1);
            }
        }
    }
}

// ---------------- weight prep: transpose + hi/lo split ----------------
__global__ void prep_w_kernel(const float* __restrict__ W_a,
                              const float* __restrict__ W_b,
                              const float* __restrict__ Wk) {
    int which = blockIdx.x;
    const float* W = which == 0 ? W_a : (which == 1 ? W_b : Wk);
    for (int idx = threadIdx.x; idx < 8192; idx += blockDim.x) {
        int n = idx >> 6, kw = idx & 63;
        float v0 = W[(2 * kw) * 128 + n];
        float v1 = W[(2 * kw + 1) * 128 + n];
        uint32_t hi, lo;
        split2(v0, v1, hi, lo);
        g_Wt[which][0][idx] = hi;
        g_Wt[which][1][idx] = lo;
    }
}

// ---------------- input prep: hi/lo split of X (k-major bf16x2 pairs) ----------------
__global__ void prep_x_kernel(const float* __restrict__ xa, const float* __restrict__ xb) {
    int idx = blockIdx.x * blockDim.x + threadIdx.x;
    if (idx >= 2 * N * 64) return;
    int type = idx >= N * 64;
    int local = idx - type * N * 64;
    const float* X = type ? xb : xa;
    int n = local >> 6, kw = local & 63;
    float2 v = *(const float2*)(X + (size_t)n * 128 + 2 * kw);
    uint32_t hi, lo;
    split2(v.x, v.y, hi, lo);
    g_Xbf[type][0][local] = hi;
    g_Xbf[type][1][local] = lo;
}

// smem u32-index layout (proj): AH, AL, WH, WL pitch-68 tiles + extra
#define SW_AH 0
#define SW_AL 8704
#define SW_WH 17408
#define SW_WL 26112
#define SW_EXTRA 34816
#define MM_SMEM_BYTES ((34816 + 512) * 4)

// sem layout: AH, WH, WL + extra
#define SEM_AH 0
#define SEM_WH 8704
#define SEM_WL 17408
#define SEM_EXTRA 26112
#define SEM_SMEM_BYTES ((26112 + 512) * 4)

// ---------------- projection: H = X@W + b, fused per-head attention dots ----------------
__global__ void __launch_bounds__(256) proj_mma_kernel(
    int type, const float* __restrict__ bias,
    const float* __restrict__ attS0, const float* __restrict__ attS1,
    const float* __restrict__ attD0, const float* __restrict__ attD1,
    int rS0, int rS1, int rD0, int rD1) {
    extern __shared__ uint32_t smemu[];
    float* smemf = (float*)smemu;
    float* satt = smemf + SW_EXTRA;
    uint32_t sb = smem_u32(smemu);

    int t = threadIdx.x;
    for (int i = t; i < 512; i += 256) {
        int arr = i >> 7, col = i & 127;
        const float* p = arr == 0 ? attS0 : arr == 1 ? attS1 : arr == 2 ? attD0 : attD1;
        satt[i] = __ldg(&p[col]);
    }

    int row0 = blockIdx.x * 128;
    stage_tile(sb + SW_AH * 4, g_Xbf[type][0], row0, N);
    stage_tile(sb + SW_AL * 4, g_Xbf[type][1], row0, N);
    stage_tile(sb + SW_WH * 4, g_Wt[type][0], 0, 128);
    stage_tile(sb + SW_WL * 4, g_Wt[type][1], 0, 128);
    CP_COMMIT_WAIT();
    __syncthreads();

    float acc[64];
    const int AO[3] = {SW_AH, SW_AH, SW_AL};
    const int WO[3] = {SW_WH, SW_WL, SW_WH};
    gemm_compute<3>(smemu, AO, WO, acc);

    float* Hout = type == 0 ? g_h_a : g_h_b;
    int wid = t >> 5, lane = t & 31;
    int wr = (wid >> 1) * 32, wc = (wid & 1) * 64;

    __syncthreads();  // done reading A/W smem; reuse as vbuf

    // phase 1: add bias, store H to global, stage v into smem (pitch 134)
#pragma unroll
    for (int rt = 0; rt < 2; rt++) {
#pragma unroll
        for (int hr = 0; hr < 2; hr++) {
            int lrow = wr + rt * 16 + hr * 8 + (lane >> 2);
            int grow = row0 + lrow;
#pragma unroll
            for (int nt = 0; nt < 8; nt++) {
                int col = wc + nt * 8 + (lane & 3) * 2;
                float2 bb = __ldg((const float2*)(bias + col));
                float v0 = acc[(rt * 8 + nt) * 4 + hr * 2] + bb.x;
                float v1 = acc[(rt * 8 + nt) * 4 + hr * 2 + 1] + bb.y;
                if (grow < N)
                    *(float2*)(Hout + (size_t)grow * 128 + col) = make_float2(v0, v1);
                *(float2*)(smemf + lrow * 134 + col) = make_float2(v0, v1);
            }
        }
    }
    __syncthreads();

    // phase 2: per-row per-head attention dots
    if (t < 128) {
        int node = row0 + t;
        if (node < N) {
            const float* vrow = smemf + t * 134;
            float* aS0 = &g_alphaS[rS0][0];
            float* aS1 = &g_alphaS[rS1][0];
            float* aD0 = &g_alphaD[rD0][0];
            float* aD1 = &g_alphaD[rD1][0];
#pragma unroll
            for (int h = 0; h < 8; h++) {
                float p0 = 0.f, p1 = 0.f, p2 = 0.f, p3 = 0.f;
#pragma unroll
                for (int i = 0; i < 16; i++) {
                    int col = h * 16 + i;
                    float v = vrow[col];
                    p0 = fmaf(v, satt[0 * 128 + col], p0);
                    p1 = fmaf(v, satt[1 * 128 + col], p1);
                    p2 = fmaf(v, satt[2 * 128 + col], p2);
                    p3 = fmaf(v, satt[3 * 128 + col], p3);
                }
                aS0[node * 8 + h] = p0;
                aS1[node * 8 + h] = p1;
                aD0[node * 8 + h] = p2;
                aD1[node * 8 + h] = p3;
            }
        }
    }
}

// ---------------- semantic score: sum_n tanh(o_n @ Wk + bk) . q ----------------
__global__ void __launch_bounds__(256, 2) sem_mma_kernel(
    const float* __restrict__ bk, const float* __restrict__ q) {
    extern __shared__ uint32_t smemu[];
    float* red = (float*)smemu + SEM_EXTRA;
    uint32_t sb = smem_u32(smemu);
    int rel = blockIdx.y;
    int row0 = blockIdx.x * 128;

    stage_tile(sb + SEM_AH * 4, g_obf[rel], row0, N);
    stage_tile(sb + SEM_WH * 4, g_Wt[2][0], 0, 128);
    stage_tile(sb + SEM_WL * 4, g_Wt[2][1], 0, 128);
    CP_COMMIT_WAIT();
    __syncthreads();

    float acc[64];
    const int AO[2] = {SEM_AH, SEM_AH};
    const int WO[2] = {SEM_WH, SEM_WL};
    gemm_compute<2>(smemu, AO, WO, acc);

    int t = threadIdx.x;
    int wid = t >> 5, lane = t & 31;
    int wr = (wid >> 1) * 32, wc = (wid & 1) * 64;

    float local = 0.f;
#pragma unroll
    for (int rt = 0; rt < 2; rt++) {
#pragma unroll
        for (int hr = 0; hr < 2; hr++) {
            int grow = row0 + wr + rt * 16 + hr * 8 + (lane >> 2);
            if (grow < N) {
#pragma unroll
                for (int nt = 0; nt < 8; nt++) {
                    int col = wc + nt * 8 + (lane & 3) * 2;
                    float2 bb = __ldg((const float2*)(bk + col));
                    float2 qq = __ldg((const float2*)(q + col));
                    float v0 = acc[(rt * 8 + nt) * 4 + hr * 2] + bb.x;
                    float v1 = acc[(rt * 8 + nt) * 4 + hr * 2 + 1] + bb.y;
                    local += tanhf(v0) * qq.x + tanhf(v1) * qq.y;
                }
            }
        }
    }
#pragma unroll
    for (int off = 16; off >= 1; off >>= 1)
        local += __shfl_down_sync(0xffffffff, local, off);
    __syncthreads();
    if (lane == 0) red[wid] = local;
    __syncthreads();
    if (t == 0) {
        float s = 0.f;
#pragma unroll
        for (int w = 0; w < 8; w++) s += red[w];
        atomicAdd(&g_score[rel], s);
    }
}

// ---------------- init ----------------
__global__ void init_kernel() {
    int i = blockIdx.x * blockDim.x + threadIdx.x;
    int stride = gridDim.x * blockDim.x;
    int* degf = &g_deg[0][0];
    for (int k = i; k < 4 * N; k += stride) degf[k] = 0;
    if (i < 4) g_score[i] = 0.f;
    if (i < 2 * HID) {
        (&g_bnsum[0][0])[i] = 0.f;
        (&g_bnsq[0][0])[i] = 0.f;
    }
}

// ---------------- CSR build ----------------
__global__ void count_kernel(const int* __restrict__ e0, const int* __restrict__ e1,
                             const int* __restrict__ e2, const int* __restrict__ e3) {
    int rel = blockIdx.y;
    const int* ei = rel == 0 ? e0 : rel == 1 ? e1 : rel == 2 ? e2 : e3;
    int e = blockIdx.x * blockDim.x + threadIdx.x;
    if (e < E) atomicAdd(&g_deg[rel][ei[E + e]], 1);
}

__global__ void scan1_kernel() {
    int rel = blockIdx.y;
    int i = blockIdx.x * 1024 + threadIdx.x;
    int lane = threadIdx.x & 31, wid = threadIdx.x >> 5;
    int v = (i < N) ? g_deg[rel][i] : 0;
    int x = v;
#pragma unroll
    for (int o = 1; o < 32; o <<= 1) {
        int y = __shfl_up_sync(0xffffffff, x, o);
        if (lane >= o) x += y;
    }
    __shared__ int ws[32];
    if (lane == 31) ws[wid] = x;
    __syncthreads();
    if (wid == 0) {
        int s = ws[lane];
#pragma unroll
        for (int o = 1; o < 32; o <<= 1) {
            int y = __shfl_up_sync(0xffffffff, s, o);
            if (lane >= o) s += y;
        }
        ws[lane] = s;
    }
    __syncthreads();
    int incl = x + (wid ? ws[wid - 1] : 0);
    if (i < N) g_rowptr[rel][i] = incl - v;
    if (threadIdx.x == 1023) g_bsum[rel][blockIdx.x] = incl;
}

__global__ void scan2_kernel() {
    int rel = blockIdx.x;
    int t = threadIdx.x;  // 128
    int lane = t & 31, wid = t >> 5;
    int v = (t < 98) ? g_bsum[rel][t] : 0;
    int x = v;
#pragma unroll
    for (int o = 1; o < 32; o <<= 1) {
        int y = __shfl_up_sync(0xffffffff, x, o);
        if (lane >= o) x += y;
    }
    __shared__ int ws[4];
    if (lane == 31) ws[wid] = x;
    __syncthreads();
    int prefix = 0;
    for (int k = 0; k < wid; k++) prefix += ws[k];
    int incl = x + prefix;
    if (t < 98) g_boff[rel][t] = incl - v;
    if (t == 0) g_rowptr[rel][N] = E;
}

__global__ void scan3_kernel() {
    int rel = blockIdx.y;
    int i = blockIdx.x * 1024 + threadIdx.x;
    if (i < N) {
        g_rowptr[rel][i] += g_boff[rel][blockIdx.x];
        g_deg[rel][i] = 0;  // reset cursor for scatter
    }
}

__global__ void scatter_kernel(const int* __restrict__ e0, const int* __restrict__ e1,
                               const int* __restrict__ e2, const int* __restrict__ e3) {
    int rel = blockIdx.y;
    const int* ei = rel == 0 ? e0 : rel == 1 ? e1 : rel == 2 ? e2 : e3;
    int e = blockIdx.x * blockDim.x + threadIdx.x;
    if (e < E) {
        int s = ei[e], d = ei[E + e];
        int pos = g_rowptr[rel][d] + atomicAdd(&g_deg[rel][d], 1);
        g_srcs[rel][pos] = s;
    }
}

// ---------------- single-pass fused softmax aggregate ----------------
// one warp per dst node; lane l handles dims [4l,4l+4), head = l/4
__global__ void aggregate_kernel() {
    int rel = blockIdx.y;
    const float* hs = (rel == 0 || rel == 2) ? g_h_a : g_h_b;
    int n = (blockIdx.x * blockDim.x + threadIdx.x) >> 5;
    if (n >= N) return;
    int lane = threadIdx.x & 31;
    int h = lane >> 2;

    const float* aS = g_alphaS[rel];
    float ad = g_alphaD[rel][n * 8 + h];
    int beg = g_rowptr[rel][n], end = g_rowptr[rel][n + 1];
    const int* srcs = g_srcs[rel];

    float den = 0.f;
    float4 acc = make_float4(0.f, 0.f, 0.f, 0.f);
    for (int e = beg; e < end; e++) {
        int s = srcs[e];
        float a = aS[s * 8 + h] + ad;
        a = a > 0.f ? a : 0.2f * a;
        float w = __expf(a);
        den += w;
        float4 hv = *reinterpret_cast<const float4*>(hs + (size_t)s * 128 + lane * 4);
        acc.x = fmaf(w, hv.x, acc.x);
        acc.y = fmaf(w, hv.y, acc.y);
        acc.z = fmaf(w, hv.z, acc.z);
        acc.w = fmaf(w, hv.w, acc.w);
    }
    float inv = 1.f / (den + 1e-16f);
    float4 outv = make_float4(fmaxf(acc.x * inv, 0.f), fmaxf(acc.y * inv, 0.f),
                              fmaxf(acc.z * inv, 0.f), fmaxf(acc.w * inv, 0.f));
    *reinterpret_cast<float4*>(&g_o[rel][(size_t)n * 128 + lane * 4]) = outv;
    // bf16 copy for the semantic GEMM
    uint32_t p0 = bfpair(outv.x, outv.y);
    uint32_t p1 = bfpair(outv.z, outv.w);
    *reinterpret_cast<uint2*>(&g_obf[rel][(size_t)n * 64 + lane * 2]) = make_uint2(p0, p1);
}

// ---------------- semantic softmax ----------------
__global__ void attn_kernel() {
    float sa0 = g_score[1] / (float)N, sa1 = g_score[2] / (float)N;
    float ma = fmaxf(sa0, sa1);
    float ea0 = expf(sa0 - ma), ea1 = expf(sa1 - ma);
    g_attn[0] = ea0 / (ea0 + ea1);
    g_attn[1] = ea1 / (ea0 + ea1);
    float sb0 = g_score[0] / (float)N, sb1 = g_score[3] / (float)N;
    float mb = fmaxf(sb0, sb1);
    float eb0 = expf(sb0 - mb), eb1 = expf(sb1 - mb);
    g_attn[2] = eb0 / (eb0 + eb1);
    g_attn[3] = eb1 / (eb0 + eb1);
}

// ---------------- combine + BN stats ----------------
#define ROWS_PER 256
__global__ void combine_kernel(float* __restrict__ outbuf, int type) {
    int j = threadIdx.x;  // 128
    int r0 = blockIdx.x * ROWS_PER;
    const float* o0;
    const float* o1;
    float a0, a1;
    if (type == 0) { o0 = g_o[1]; o1 = g_o[2]; a0 = g_attn[0]; a1 = g_attn[1]; }
    else           { o0 = g_o[0]; o1 = g_o[3]; a0 = g_attn[2]; a1 = g_attn[3]; }
    float s = 0.f, sq = 0.f;
    int rend = r0 + ROWS_PER;
    if (rend > N) rend = N;
    for (int r = r0; r < rend; r++) {
        float c = a0 * o0[(size_t)r * 128 + j] + a1 * o1[(size_t)r * 128 + j];
        outbuf[(size_t)r * 128 + j] = c;
        s += c;
        sq += c * c;
    }
    atomicAdd(&g_bnsum[type][j], s);
    atomicAdd(&g_bnsq[type][j], sq);
}

__global__ void bnparam_kernel(const float* __restrict__ gamma,
                               const float* __restrict__ beta) {
    int t = threadIdx.x;  // 256
    int type = t >> 7, j = t & 127;
    float mu = g_bnsum[type][j] / (float)N;
    float var = g_bnsq[type][j] / (float)N - mu * mu;
    float rstd = rsqrtf(var + 1e-5f);
    float sc = rstd * gamma[j];
    g_scale[type][j] = sc;
    g_shift[type][j] = beta[j] - mu * sc;
}

__global__ void normalize_kernel(float* __restrict__ out) {
    int stride = gridDim.x * blockDim.x;
    int total = 2 * N * 32;  // float4 elements
    for (int i = blockIdx.x * blockDim.x + threadIdx.x; i < total; i += stride) {
        int j4 = i & 31;
        int type = (i >= N * 32) ? 1 : 0;
        float4 v = ((float4*)out)[i];
        int j = j4 * 4;
        const float* sc = g_scale[type];
        const float* sf = g_shift[type];
        v.x = v.x * sc[j + 0] + sf[j + 0];
        v.y = v.y * sc[j + 1] + sf[j + 1];
        v.z = v.z * sc[j + 2] + sf[j + 2];
        v.w = v.w * sc[j + 3] + sf[j + 3];
        ((float4*)out)[i] = v;
    }
}

// ---------------- host ----------------
extern "C" void kernel_launch(void* const* d_in, const int* in_sizes, int n_in,
                              void* d_out, int out_size) {
    const float* x_a = (const float*)d_in[0];
    const float* x_b = (const float*)d_in[1];
    const int* ei_ab = (const int*)d_in[2];
    const int* ei_ba = (const int*)d_in[3];
    const int* ei_aa = (const int*)d_in[4];
    const int* ei_bb = (const int*)d_in[5];
    const float* W_a = (const float*)d_in[6];
    const float* b_a = (const float*)d_in[7];
    const float* W_b = (const float*)d_in[8];
    const float* b_b = (const float*)d_in[9];
    const float* att_ab_s = (const float*)d_in[10];
    const float* att_ab_d = (const float*)d_in[11];
    const float* att_ba_s = (const float*)d_in[12];
    const float* att_ba_d = (const float*)d_in[13];
    const float* att_aa_s = (const float*)d_in[14];
    const float* att_aa_d = (const float*)d_in[15];
    const float* att_bb_s = (const float*)d_in[16];
    const float* att_bb_d = (const float*)d_in[17];
    const float* Wk = (const float*)d_in[18];
    const float* bk = (const float*)d_in[19];
    const float* q  = (const float*)d_in[20];
    const float* gamma = (const float*)d_in[21];
    const float* beta  = (const float*)d_in[22];
    float* out = (float*)d_out;

    cudaFuncSetAttribute(proj_mma_kernel, cudaFuncAttributeMaxDynamicSharedMemorySize, MM_SMEM_BYTES);
    cudaFuncSetAttribute(sem_mma_kernel, cudaFuncAttributeMaxDynamicSharedMemorySize, SEM_SMEM_BYTES);

    init_kernel<<<512, 256>>>();
    prep_w_kernel<<<3, 256>>>(W_a, W_b, Wk);
    prep_x_kernel<<<(2 * N * 64 + 255) / 256, 256>>>(x_a, x_b);

    // relations: 0=ab(src a,dst b) 1=ba(src b,dst a) 2=aa 3=bb
    int mmGrid = (N + 127) / 128;  // 782
    // type a: S-dots for rels 0,2 ; D-dots for rels 1,2
    proj_mma_kernel<<<mmGrid, 256, MM_SMEM_BYTES>>>(
        0, b_a, att_ab_s, att_aa_s, att_ba_d, att_aa_d, 0, 2, 1, 2);
    // type b: S-dots for rels 1,3 ; D-dots for rels 0,3
    proj_mma_kernel<<<mmGrid, 256, MM_SMEM_BYTES>>>(
        1, b_b, att_ba_s, att_bb_s, att_ab_d, att_bb_d, 1, 3, 0, 3);

    dim3 eGrid((E + 255) / 256, 4);
    count_kernel<<<eGrid, 256>>>(ei_ab, ei_ba, ei_aa, ei_bb);

    dim3 sGrid((N + 1023) / 1024, 4);
    scan1_kernel<<<sGrid, 1024>>>();
    scan2_kernel<<<4, 128>>>();
    scan3_kernel<<<sGrid, 1024>>>();

    scatter_kernel<<<eGrid, 256>>>(ei_ab, ei_ba, ei_aa, ei_bb);

    dim3 aggGrid((N * 32 + 255) / 256, 4);
    aggregate_kernel<<<aggGrid, 256>>>();

    dim3 semGrid(mmGrid, 4);
    sem_mma_kernel<<<semGrid, 256, SEM_SMEM_BYTES>>>(bk, q);

    attn_kernel<<<1, 1>>>();

    int cGrid = (N + ROWS_PER - 1) / ROWS_PER;
    combine_kernel<<<cGrid, 128>>>(out, 0);
    combine_kernel<<<cGrid, 128>>>(out + (size_t)N * HID, 1);

    bnparam_kernel<<<1, 256>>>(gamma, beta);

    normalize_kernel<<<4096, 256>>>(out);
}

// round 6
// speedup vs baseline: 2.5535x; 1.6297x over previous
#include <cuda_runtime.h>
#include <cuda_bf16.h>
#include <math.h>
#include <stdint.h>

#define N 100000
#define E 400000
#define HID 128
#define NH 8

// ---------------- device scratch ----------------
__device__ __align__(16) float g_h_a[(size_t)N * HID];
__device__ __align__(16) float g_h_b[(size_t)N * HID];
__device__ __align__(16) float g_alphaS[4][(size_t)N * NH];  // [n*8 + h]
__device__ __align__(16) float g_alphaD[4][(size_t)N * NH];
__device__ int   g_deg[4][N];
__device__ int   g_rowptr[4][N + 1];
__device__ int   g_bsum[4][128];
__device__ int   g_boff[4][128];
__device__ int   g_srcs[4][E];
__device__ __align__(16) float g_o[4][(size_t)N * HID];
__device__ __align__(16) uint32_t g_obf[4][(size_t)N * 64];   // bf16x2 copy of o
__device__ float g_score[4];
__device__ float g_attn[4];
__device__ float g_st[2][5][HID];   // s0,s1,ss0,ss1,cross per type per column
__device__ float g_scale[2][HID];
__device__ float g_shift[2][HID];
// W as pre-packed MMA B-fragments: [which][hi/lo][((whalf*8+nt)*8+kc)*32+lane] = {b0,b1}
__device__ __align__(16) uint2 g_Wfrag[3][2][4096];

// ---------------- helpers ----------------
__device__ __forceinline__ uint32_t bfpair(float x, float y) {
    __nv_bfloat162 p = __floats2bfloat162_rn(x, y);
    return *reinterpret_cast<uint32_t*>(&p);
}

__device__ __forceinline__ void split2(float x, float y, uint32_t& hi, uint32_t& lo) {
    __nv_bfloat16 hx = __float2bfloat16(x), hy = __float2bfloat16(y);
    __nv_bfloat162 hp(hx, hy);
    hi = *reinterpret_cast<uint32_t*>(&hp);
    float lx = x - __bfloat162float(hx);
    float ly = y - __bfloat162float(hy);
    lo = bfpair(lx, ly);
}

__device__ __forceinline__ void unpack_bf2(uint32_t u, float& a, float& b) {
    __nv_bfloat162 p = *reinterpret_cast<__nv_bfloat162*>(&u);
    a = __bfloat162float(p.x);
    b = __bfloat162float(p.y);
}

__device__ __forceinline__ void mma_bf16(float* d, const uint32_t* a, uint32_t b0, uint32_t b1) {
    asm volatile(
        "mma.sync.aligned.m16n8k16.row.col.f32.bf16.bf16.f32 "
        "{%0,%1,%2,%3}, {%4,%5,%6,%7}, {%8,%9}, {%0,%1,%2,%3};"
        : "+f"(d[0]), "+f"(d[1]), "+f"(d[2]), "+f"(d[3])
        : "r"(a[0]), "r"(a[1]), "r"(a[2]), "r"(a[3]), "r"(b0), "r"(b1));
}

__device__ __forceinline__ uint32_t smem_u32(const void* p) {
    uint32_t a;
    asm("{ .reg .u64 t; cvta.to.shared.u64 t, %1; cvt.u32.u64 %0, t; }" : "=r"(a) : "l"(p));
    return a;
}

// stage a 128-row x 64-u32 tile (pitch 68 u32) from global via cp.async, 16B chunks
__device__ __forceinline__ void stage_tile(uint32_t sbase_bytes, const uint32_t* __restrict__ src,
                                           int row0, int arows) {
    int t = threadIdx.x;
#pragma unroll
    for (int i = 0; i < 8; i++) {
        int idx = i * 256 + t;            // [0, 2048)
        int r = idx >> 4, c = idx & 15;
        int gr = row0 + r;
        bool ok = (gr < arows);
        const uint32_t* s = src + (size_t)(ok ? gr : 0) * 64 + c * 4;
        uint32_t dst = sbase_bytes + (r * 68 + c * 4) * 4;
        int sz = ok ? 16 : 0;
        asm volatile("cp.async.cg.shared.global [%0], [%1], 16, %2;" :: "r"(dst), "l"(s), "r"(sz));
    }
}

#define CP_COMMIT_WAIT() do { \
    asm volatile("cp.async.commit_group;" ::: "memory"); \
    asm volatile("cp.async.wait_group 0;" ::: "memory"); \
} while (0)

// ---------------- GEMM compute on staged A tiles + global W fragments ----------------
// 8 warps; warp tile 32 rows x 64 cols; acc[(rt*8+nt)*4 + r]
template <int NPASS>
__device__ __forceinline__ void gemm_compute(const uint32_t* __restrict__ smemu,
                                             const int* AO, const uint2* const* WF,
                                             float* acc) {
    int t = threadIdx.x;
    int wid = t >> 5, lane = t & 31;
    int wr = (wid >> 1) * 32, whalf = wid & 1;

#pragma unroll
    for (int i = 0; i < 64; i++) acc[i] = 0.f;

#pragma unroll
    for (int p = 0; p < NPASS; p++) {
        const uint32_t* Ab = smemu + AO[p] + (wr + (lane >> 2)) * 68 + (lane & 3);
        const uint2* Wb = WF[p] + whalf * 2048 + lane;
#pragma unroll 2
        for (int kc = 0; kc < 8; kc++) {
            uint32_t a[2][4];
#pragma unroll
            for (int rt = 0; rt < 2; rt++) {
                const uint32_t* Ap = Ab + rt * 16 * 68 + kc * 8;
                a[rt][0] = Ap[0];
                a[rt][1] = Ap[8 * 68];
                a[rt][2] = Ap[4];
                a[rt][3] = Ap[8 * 68 + 4];
            }
#pragma unroll
            for (int nt = 0; nt < 8; nt++) {
                uint2 b = __ldg(&Wb[(nt * 8 + kc) * 32]);
                mma_bf16(acc + (0 * 8 + nt) * 4, a[0], b.x, b.y);
                mma_bf16(acc + (1 * 8 + nt) * 4, a[1], b.x, b.y);
            }
        }
    }
}

// ---------------- weight prep: pack hi/lo MMA B fragments ----------------
__global__ void prep_w_kernel(const float* __restrict__ W_a,
                              const float* __restrict__ W_b,
                              const float* __restrict__ Wk) {
    int which = blockIdx.x;
    const float* W = which == 0 ? W_a : (which == 1 ? W_b : Wk);
    for (int i = threadIdx.x; i < 4096; i += blockDim.x) {
        int lane = i & 31;
        int kc = (i >> 5) & 7;
        int nt = (i >> 8) & 7;
        int whalf = (i >> 11) & 1;
        int n = whalf * 64 + nt * 8 + (lane >> 2);
        int kw0 = kc * 8 + (lane & 3);
        int kw1 = kw0 + 4;
        float x0 = W[(2 * kw0) * 128 + n], x1 = W[(2 * kw0 + 1) * 128 + n];
        float y0 = W[(2 * kw1) * 128 + n], y1 = W[(2 * kw1 + 1) * 128 + n];
        uint32_t xh, xl, yh, yl;
        split2(x0, x1, xh, xl);
        split2(y0, y1, yh, yl);
        g_Wfrag[which][0][i] = make_uint2(xh, yh);
        g_Wfrag[which][1][i] = make_uint2(xl, yl);
    }
}

// smem u32-index layout (proj): AH, AL pitch-68 tiles + satt
#define SW_AH 0
#define SW_AL 8704
#define SW_SATT 17408
#define PROJ_SMEM_BYTES ((17408 + 512) * 4)

// sem layout: AH + red
#define SEM_RED 8704
#define SEM_SMEM_BYTES ((8704 + 64) * 4)

// ---------------- projection: H = X@W + b, fused per-head attention dots ----------------
__global__ void __launch_bounds__(256, 2) proj_mma_kernel(
    const float* __restrict__ X, int type, const float* __restrict__ bias,
    const float* __restrict__ attS0, const float* __restrict__ attS1,
    const float* __restrict__ attD0, const float* __restrict__ attD1,
    int rS0, int rS1, int rD0, int rD1) {
    extern __shared__ uint32_t smemu[];
    float* smemf = (float*)smemu;
    float* satt = smemf + SW_SATT;

    int t = threadIdx.x;
    for (int i = t; i < 512; i += 256) {
        int arr = i >> 7, col = i & 127;
        const float* p = arr == 0 ? attS0 : arr == 1 ? attS1 : arr == 2 ? attD0 : attD1;
        satt[i] = __ldg(&p[col]);
    }

    int row0 = blockIdx.x * 128;
    // stage A with inline hi/lo split
    const float4* X4 = (const float4*)X;
#pragma unroll
    for (int i = 0; i < 16; i++) {
        int idx = i * 256 + t;            // [0, 4096)
        int r = idx >> 5, c4 = idx & 31;
        int gr = row0 + r;
        float4 v = make_float4(0.f, 0.f, 0.f, 0.f);
        if (gr < N) v = X4[(size_t)gr * 32 + c4];
        uint32_t h0, l0, h1, l1;
        split2(v.x, v.y, h0, l0);
        split2(v.z, v.w, h1, l1);
        int base = r * 68 + c4 * 2;
        smemu[SW_AH + base] = h0;
        smemu[SW_AH + base + 1] = h1;
        smemu[SW_AL + base] = l0;
        smemu[SW_AL + base + 1] = l1;
    }
    __syncthreads();

    float acc[64];
    const int AO[3] = {SW_AH, SW_AH, SW_AL};
    const uint2* WF[3] = {g_Wfrag[type][0], g_Wfrag[type][1], g_Wfrag[type][0]};
    gemm_compute<3>(smemu, AO, WF, acc);

    float* Hout = type == 0 ? g_h_a : g_h_b;
    int wid = t >> 5, lane = t & 31;
    int wr = (wid >> 1) * 32, wc = (wid & 1) * 64;

    __syncthreads();  // done reading A smem; reuse as vbuf (pitch 134 floats)

#pragma unroll
    for (int rt = 0; rt < 2; rt++) {
#pragma unroll
        for (int hr = 0; hr < 2; hr++) {
            int lrow = wr + rt * 16 + hr * 8 + (lane >> 2);
            int grow = row0 + lrow;
#pragma unroll
            for (int nt = 0; nt < 8; nt++) {
                int col = wc + nt * 8 + (lane & 3) * 2;
                float2 bb = __ldg((const float2*)(bias + col));
                float v0 = acc[(rt * 8 + nt) * 4 + hr * 2] + bb.x;
                float v1 = acc[(rt * 8 + nt) * 4 + hr * 2 + 1] + bb.y;
                if (grow < N)
                    *(float2*)(Hout + (size_t)grow * 128 + col) = make_float2(v0, v1);
                *(float2*)(smemf + lrow * 134 + col) = make_float2(v0, v1);
            }
        }
    }
    __syncthreads();

    if (t < 128) {
        int node = row0 + t;
        if (node < N) {
            const float* vrow = smemf + t * 134;
            float* aS0 = &g_alphaS[rS0][0];
            float* aS1 = &g_alphaS[rS1][0];
            float* aD0 = &g_alphaD[rD0][0];
            float* aD1 = &g_alphaD[rD1][0];
#pragma unroll
            for (int h = 0; h < 8; h++) {
                float p0 = 0.f, p1 = 0.f, p2 = 0.f, p3 = 0.f;
#pragma unroll
                for (int i = 0; i < 16; i++) {
                    int col = h * 16 + i;
                    float v = vrow[col];
                    p0 = fmaf(v, satt[0 * 128 + col], p0);
                    p1 = fmaf(v, satt[1 * 128 + col], p1);
                    p2 = fmaf(v, satt[2 * 128 + col], p2);
                    p3 = fmaf(v, satt[3 * 128 + col], p3);
                }
                aS0[node * 8 + h] = p0;
                aS1[node * 8 + h] = p1;
                aD0[node * 8 + h] = p2;
                aD1[node * 8 + h] = p3;
            }
        }
    }
}

// ---------------- semantic score: sum_n tanh(o_n @ Wk + bk) . q ----------------
__global__ void __launch_bounds__(256, 2) sem_mma_kernel(
    const float* __restrict__ bk, const float* __restrict__ q) {
    extern __shared__ uint32_t smemu[];
    float* red = (float*)smemu + SEM_RED;
    uint32_t sb = smem_u32(smemu);
    int rel = blockIdx.y;
    int row0 = blockIdx.x * 128;

    stage_tile(sb, g_obf[rel], row0, N);
    CP_COMMIT_WAIT();
    __syncthreads();

    float acc[64];
    const int AO[2] = {0, 0};
    const uint2* WF[2] = {g_Wfrag[2][0], g_Wfrag[2][1]};
    gemm_compute<2>(smemu, AO, WF, acc);

    int t = threadIdx.x;
    int wid = t >> 5, lane = t & 31;
    int wr = (wid >> 1) * 32, wc = (wid & 1) * 64;

    float local = 0.f;
#pragma unroll
    for (int rt = 0; rt < 2; rt++) {
#pragma unroll
        for (int hr = 0; hr < 2; hr++) {
            int grow = row0 + wr + rt * 16 + hr * 8 + (lane >> 2);
            if (grow < N) {
#pragma unroll
                for (int nt = 0; nt < 8; nt++) {
                    int col = wc + nt * 8 + (lane & 3) * 2;
                    float2 bb = __ldg((const float2*)(bk + col));
                    float2 qq = __ldg((const float2*)(q + col));
                    float v0 = acc[(rt * 8 + nt) * 4 + hr * 2] + bb.x;
                    float v1 = acc[(rt * 8 + nt) * 4 + hr * 2 + 1] + bb.y;
                    local += tanhf(v0) * qq.x + tanhf(v1) * qq.y;
                }
            }
        }
    }
#pragma unroll
    for (int off = 16; off >= 1; off >>= 1)
        local += __shfl_down_sync(0xffffffff, local, off);
    __syncthreads();
    if (lane == 0) red[wid] = local;
    __syncthreads();
    if (t == 0) {
        float s = 0.f;
#pragma unroll
        for (int w = 0; w < 8; w++) s += red[w];
        atomicAdd(&g_score[rel], s);
    }
}

// ---------------- init ----------------
__global__ void init_kernel() {
    int i = blockIdx.x * blockDim.x + threadIdx.x;
    int stride = gridDim.x * blockDim.x;
    int* degf = &g_deg[0][0];
    for (int k = i; k < 4 * N; k += stride) degf[k] = 0;
    if (i < 4) g_score[i] = 0.f;
    if (i < 2 * 5 * HID) (&g_st[0][0][0])[i] = 0.f;
}

// ---------------- CSR build ----------------
__global__ void count_kernel(const int* __restrict__ e0, const int* __restrict__ e1,
                             const int* __restrict__ e2, const int* __restrict__ e3) {
    int rel = blockIdx.y;
    const int* ei = rel == 0 ? e0 : rel == 1 ? e1 : rel == 2 ? e2 : e3;
    int e = blockIdx.x * blockDim.x + threadIdx.x;
    if (e < E) atomicAdd(&g_deg[rel][ei[E + e]], 1);
}

__global__ void scan1_kernel() {
    int rel = blockIdx.y;
    int i = blockIdx.x * 1024 + threadIdx.x;
    int lane = threadIdx.x & 31, wid = threadIdx.x >> 5;
    int v = (i < N) ? g_deg[rel][i] : 0;
    int x = v;
#pragma unroll
    for (int o = 1; o < 32; o <<= 1) {
        int y = __shfl_up_sync(0xffffffff, x, o);
        if (lane >= o) x += y;
    }
    __shared__ int ws[32];
    if (lane == 31) ws[wid] = x;
    __syncthreads();
    if (wid == 0) {
        int s = ws[lane];
#pragma unroll
        for (int o = 1; o < 32; o <<= 1) {
            int y = __shfl_up_sync(0xffffffff, s, o);
            if (lane >= o) s += y;
        }
        ws[lane] = s;
    }
    __syncthreads();
    int incl = x + (wid ? ws[wid - 1] : 0);
    if (i < N) g_rowptr[rel][i] = incl - v;
    if (threadIdx.x == 1023) g_bsum[rel][blockIdx.x] = incl;
}

__global__ void scan2_kernel() {
    int rel = blockIdx.x;
    int t = threadIdx.x;  // 128
    int lane = t & 31, wid = t >> 5;
    int v = (t < 98) ? g_bsum[rel][t] : 0;
    int x = v;
#pragma unroll
    for (int o = 1; o < 32; o <<= 1) {
        int y = __shfl_up_sync(0xffffffff, x, o);
        if (lane >= o) x += y;
    }
    __shared__ int ws[4];
    if (lane == 31) ws[wid] = x;
    __syncthreads();
    int prefix = 0;
    for (int k = 0; k < wid; k++) prefix += ws[k];
    int incl = x + prefix;
    if (t < 98) g_boff[rel][t] = incl - v;
    if (t == 0) g_rowptr[rel][N] = E;
}

__global__ void scan3_kernel() {
    int rel = blockIdx.y;
    int i = blockIdx.x * 1024 + threadIdx.x;
    if (i < N) {
        g_rowptr[rel][i] += g_boff[rel][blockIdx.x];
        g_deg[rel][i] = 0;  // reset cursor for scatter
    }
}

__global__ void scatter_kernel(const int* __restrict__ e0, const int* __restrict__ e1,
                               const int* __restrict__ e2, const int* __restrict__ e3) {
    int rel = blockIdx.y;
    const int* ei = rel == 0 ? e0 : rel == 1 ? e1 : rel == 2 ? e2 : e3;
    int e = blockIdx.x * blockDim.x + threadIdx.x;
    if (e < E) {
        int s = ei[e], d = ei[E + e];
        int pos = g_rowptr[rel][d] + atomicAdd(&g_deg[rel][d], 1);
        g_srcs[rel][pos] = s;
    }
}

// ---------------- single-pass fused softmax aggregate (2-edge unroll) ----------------
__global__ void aggregate_kernel() {
    int rel = blockIdx.y;
    const float* hs = (rel == 0 || rel == 2) ? g_h_a : g_h_b;
    int n = (blockIdx.x * blockDim.x + threadIdx.x) >> 5;
    if (n >= N) return;
    int lane = threadIdx.x & 31;
    int h = lane >> 2;

    const float* aS = g_alphaS[rel];
    float ad = g_alphaD[rel][n * 8 + h];
    int beg = g_rowptr[rel][n], end = g_rowptr[rel][n + 1];
    const int* srcs = g_srcs[rel];

    float den = 0.f;
    float4 acc = make_float4(0.f, 0.f, 0.f, 0.f);
    int e = beg;
    for (; e + 2 <= end; e += 2) {
        int s0 = srcs[e], s1 = srcs[e + 1];
        float a0 = aS[s0 * 8 + h] + ad;
        float a1 = aS[s1 * 8 + h] + ad;
        a0 = a0 > 0.f ? a0 : 0.2f * a0;
        a1 = a1 > 0.f ? a1 : 0.2f * a1;
        float w0 = __expf(a0), w1 = __expf(a1);
        den += w0 + w1;
        float4 h0 = *reinterpret_cast<const float4*>(hs + (size_t)s0 * 128 + lane * 4);
        float4 h1 = *reinterpret_cast<const float4*>(hs + (size_t)s1 * 128 + lane * 4);
        acc.x = fmaf(w0, h0.x, fmaf(w1, h1.x, acc.x));
        acc.y = fmaf(w0, h0.y, fmaf(w1, h1.y, acc.y));
        acc.z = fmaf(w0, h0.z, fmaf(w1, h1.z, acc.z));
        acc.w = fmaf(w0, h0.w, fmaf(w1, h1.w, acc.w));
    }
    if (e < end) {
        int s0 = srcs[e];
        float a0 = aS[s0 * 8 + h] + ad;
        a0 = a0 > 0.f ? a0 : 0.2f * a0;
        float w0 = __expf(a0);
        den += w0;
        float4 h0 = *reinterpret_cast<const float4*>(hs + (size_t)s0 * 128 + lane * 4);
        acc.x = fmaf(w0, h0.x, acc.x);
        acc.y = fmaf(w0, h0.y, acc.y);
        acc.z = fmaf(w0, h0.z, acc.z);
        acc.w = fmaf(w0, h0.w, acc.w);
    }
    float inv = 1.f / (den + 1e-16f);
    float4 outv = make_float4(fmaxf(acc.x * inv, 0.f), fmaxf(acc.y * inv, 0.f),
                              fmaxf(acc.z * inv, 0.f), fmaxf(acc.w * inv, 0.f));
    *reinterpret_cast<float4*>(&g_o[rel][(size_t)n * 128 + lane * 4]) = outv;
    uint32_t p0 = bfpair(outv.x, outv.y);
    uint32_t p1 = bfpair(outv.z, outv.w);
    *reinterpret_cast<uint2*>(&g_obf[rel][(size_t)n * 64 + lane * 2]) = make_uint2(p0, p1);
}

// ---------------- BN stats from bf16 o (5 stats per type per column) ----------------
__global__ void stats_kernel() {
    int type = blockIdx.y;
    int rel0 = type == 0 ? 1 : 0;
    int rel1 = type == 0 ? 2 : 3;
    int t = threadIdx.x;        // 256
    int cp = t & 63, rg = t >> 6;
    int r0 = blockIdx.x * 512;
    int rend = r0 + 512;
    if (rend > N) rend = N;

    float s0a = 0.f, s1a = 0.f, ss0a = 0.f, ss1a = 0.f, cxa = 0.f;
    float s0b = 0.f, s1b = 0.f, ss0b = 0.f, ss1b = 0.f, cxb = 0.f;
    for (int r = r0 + rg; r < rend; r += 4) {
        uint32_t u0 = g_obf[rel0][(size_t)r * 64 + cp];
        uint32_t u1 = g_obf[rel1][(size_t)r * 64 + cp];
        float xa, xb, ya, yb;
        unpack_bf2(u0, xa, xb);
        unpack_bf2(u1, ya, yb);
        s0a += xa; s1a += ya; ss0a += xa * xa; ss1a += ya * ya; cxa += xa * ya;
        s0b += xb; s1b += yb; ss0b += xb * xb; ss1b += yb * yb; cxb += xb * yb;
    }
    __shared__ float red[4][64][10];
    float* my = red[rg][cp];
    my[0] = s0a; my[1] = s1a; my[2] = ss0a; my[3] = ss1a; my[4] = cxa;
    my[5] = s0b; my[6] = s1b; my[7] = ss0b; my[8] = ss1b; my[9] = cxb;
    __syncthreads();
    if (rg == 0) {
#pragma unroll
        for (int k = 0; k < 10; k++) {
            float v = red[0][cp][k] + red[1][cp][k] + red[2][cp][k] + red[3][cp][k];
            int stat = k % 5;
            int col = cp * 2 + (k / 5);
            atomicAdd(&g_st[type][stat][col], v);
        }
    }
}

// ---------------- semantic softmax ----------------
__global__ void attn_kernel() {
    float sa0 = g_score[1] / (float)N, sa1 = g_score[2] / (float)N;
    float ma = fmaxf(sa0, sa1);
    float ea0 = expf(sa0 - ma), ea1 = expf(sa1 - ma);
    g_attn[0] = ea0 / (ea0 + ea1);
    g_attn[1] = ea1 / (ea0 + ea1);
    float sb0 = g_score[0] / (float)N, sb1 = g_score[3] / (float)N;
    float mb = fmaxf(sb0, sb1);
    float eb0 = expf(sb0 - mb), eb1 = expf(sb1 - mb);
    g_attn[2] = eb0 / (eb0 + eb1);
    g_attn[3] = eb1 / (eb0 + eb1);
}

// ---------------- BN params from stats + attn ----------------
__global__ void bnparam_kernel(const float* __restrict__ gamma,
                               const float* __restrict__ beta) {
    int t = threadIdx.x;  // 256
    int type = t >> 7, j = t & 127;
    float a0 = g_attn[type * 2 + 0], a1 = g_attn[type * 2 + 1];
    float s0 = g_st[type][0][j], s1 = g_st[type][1][j];
    float ss0 = g_st[type][2][j], ss1 = g_st[type][3][j], cx = g_st[type][4][j];
    float mu = (a0 * s0 + a1 * s1) / (float)N;
    float ex2 = (a0 * a0 * ss0 + 2.f * a0 * a1 * cx + a1 * a1 * ss1) / (float)N;
    float var = ex2 - mu * mu;
    float rstd = rsqrtf(var + 1e-5f);
    float sc = rstd * gamma[j];
    g_scale[type][j] = sc;
    g_shift[type][j] = beta[j] - mu * sc;
}

// ---------------- fused combine + normalize ----------------
__global__ void combine_norm_kernel(float* __restrict__ out) {
    int stride = gridDim.x * blockDim.x;
    int total = 2 * N * 32;  // float4 elements
    for (int i = blockIdx.x * blockDim.x + threadIdx.x; i < total; i += stride) {
        int type = (i >= N * 32) ? 1 : 0;
        int local = i - type * N * 32;
        const float4* o0 = (const float4*)(type == 0 ? g_o[1] : g_o[0]);
        const float4* o1 = (const float4*)(type == 0 ? g_o[2] : g_o[3]);
        float a0 = g_attn[type * 2 + 0], a1 = g_attn[type * 2 + 1];
        float4 v0 = o0[local], v1 = o1[local];
        int j = (local & 31) * 4;
        const float* sc = g_scale[type];
        const float* sf = g_shift[type];
        float4 r;
        r.x = (a0 * v0.x + a1 * v1.x) * sc[j + 0] + sf[j + 0];
        r.y = (a0 * v0.y + a1 * v1.y) * sc[j + 1] + sf[j + 1];
        r.z = (a0 * v0.z + a1 * v1.z) * sc[j + 2] + sf[j + 2];
        r.w = (a0 * v0.w + a1 * v1.w) * sc[j + 3] + sf[j + 3];
        ((float4*)out)[i] = r;
    }
}

// ---------------- host ----------------
extern "C" void kernel_launch(void* const* d_in, const int* in_sizes, int n_in,
                              void* d_out, int out_size) {
    const float* x_a = (const float*)d_in[0];
    const float* x_b = (const float*)d_in[1];
    const int* ei_ab = (const int*)d_in[2];
    const int* ei_ba = (const int*)d_in[3];
    const int* ei_aa = (const int*)d_in[4];
    const int* ei_bb = (const int*)d_in[5];
    const float* W_a = (const float*)d_in[6];
    const float* b_a = (const float*)d_in[7];
    const float* W_b = (const float*)d_in[8];
    const float* b_b = (const float*)d_in[9];
    const float* att_ab_s = (const float*)d_in[10];
    const float* att_ab_d = (const float*)d_in[11];
    const float* att_ba_s = (const float*)d_in[12];
    const float* att_ba_d = (const float*)d_in[13];
    const float* att_aa_s = (const float*)d_in[14];
    const float* att_aa_d = (const float*)d_in[15];
    const float* att_bb_s = (const float*)d_in[16];
    const float* att_bb_d = (const float*)d_in[17];
    const float* Wk = (const float*)d_in[18];
    const float* bk = (const float*)d_in[19];
    const float* q  = (const float*)d_in[20];
    const float* gamma = (const float*)d_in[21];
    const float* beta  = (const float*)d_in[22];
    float* out = (float*)d_out;

    cudaFuncSetAttribute(proj_mma_kernel, cudaFuncAttributeMaxDynamicSharedMemorySize, PROJ_SMEM_BYTES);
    cudaFuncSetAttribute(sem_mma_kernel, cudaFuncAttributeMaxDynamicSharedMemorySize, SEM_SMEM_BYTES);

    init_kernel<<<512, 256>>>();
    prep_w_kernel<<<3, 256>>>(W_a, W_b, Wk);

    // relations: 0=ab(src a,dst b) 1=ba(src b,dst a) 2=aa 3=bb
    int mmGrid = (N + 127) / 128;  // 782
    proj_mma_kernel<<<mmGrid, 256, PROJ_SMEM_BYTES>>>(
        x_a, 0, b_a, att_ab_s, att_aa_s, att_ba_d, att_aa_d, 0, 2, 1, 2);
    proj_mma_kernel<<<mmGrid, 256, PROJ_SMEM_BYTES>>>(
        x_b, 1, b_b, att_ba_s, att_bb_s, att_ab_d, att_bb_d, 1, 3, 0, 3);

    dim3 eGrid((E + 255) / 256, 4);
    count_kernel<<<eGrid, 256>>>(ei_ab, ei_ba, ei_aa, ei_bb);

    dim3 sGrid((N + 1023) / 1024, 4);
    scan1_kernel<<<sGrid, 1024>>>();
    scan2_kernel<<<4, 128>>>();
    scan3_kernel<<<sGrid, 1024>>>();

    scatter_kernel<<<eGrid, 256>>>(ei_ab, ei_ba, ei_aa, ei_bb);

    dim3 aggGrid((N * 32 + 255) / 256, 4);
    aggregate_kernel<<<aggGrid, 256>>>();

    dim3 semGrid(mmGrid, 4);
    sem_mma_kernel<<<semGrid, 256, SEM_SMEM_BYTES>>>(bk, q);

    dim3 stGrid((N + 511) / 512, 2);
    stats_kernel<<<stGrid, 256>>>();

    attn_kernel<<<1, 1>>>();
    bnparam_kernel<<<1, 256>>>(gamma, beta);

    combine_norm_kernel<<<4096, 256>>>(out);
}